// round 14
// baseline (speedup 1.0000x reference)
#include <cuda_runtime.h>
#include <cuda_bf16.h>
#include <cuda_fp16.h>
#include <cstdint>

#define NN   50000
#define NE   800000
#define FEAT 16
#define HID  128
#define NL   4
#define NG   1024
#define OD   12
#define NBLK ((NN + 1023) / 1024)
#define BPITCH 136     // ushorts: 272B rows, LDSM.trans conflict-free (proven)
#define APITCH 12      // uint32:  48B rows (gemm-only A stage, proven)
#define FPITCH 68      // uint32: 272B rows for fused A tile (same stride as B)

// ---------------- streams / events: created at program load -----------------
struct HxStreams {
    cudaStream_t s1, s2;
    cudaEvent_t  eFork, eW, eCsr;
    HxStreams() {
        cudaStreamCreateWithFlags(&s1, cudaStreamNonBlocking);
        cudaStreamCreateWithFlags(&s2, cudaStreamNonBlocking);
        cudaEventCreateWithFlags(&eFork, cudaEventDisableTiming);
        cudaEventCreateWithFlags(&eW,    cudaEventDisableTiming);
        cudaEventCreateWithFlags(&eCsr,  cudaEventDisableTiming);
    }
};
static HxStreams g_hx;

// ---------------- scratch (device globals) ----------------------------------
__device__ uint32_t g_hwf0[NN * 64];       // half2-packed layer activations
__device__ uint32_t g_hwf1[NN * 64];
__device__ uint32_t g_A0h[NN * 64];
__device__ uint32_t g_A0l[NN * 64];
__device__ uint32_t g_A1h[NN * 64];
__device__ uint32_t g_A1l[NN * 64];
__device__ uint32_t g_Wh[5 * 8192];
__device__ uint32_t g_Wl[5 * 8192];
__device__ float    g_dinv[NN];
__device__ float    g_pool[NG * HID];
__device__ float    g_cnt[NG];
__device__ int      g_degi[NN];
__device__ int      g_rowptr[NN + 1];
__device__ int      g_fillcnt[NN];
__device__ int      g_csr[NE];
__device__ int      g_bsum[64];

__device__ __forceinline__ void red_add_f4(float* p, float4 v) {
    asm volatile("red.global.add.v4.f32 [%0], {%1,%2,%3,%4};"
                 :: "l"(p), "f"(v.x), "f"(v.y), "f"(v.z), "f"(v.w)
                 : "memory");
}

__device__ __forceinline__ uint32_t smem_u32(const void* p) {
    uint32_t a;
    asm("{ .reg .u64 t; cvta.to.shared.u64 t, %1; cvt.u32.u64 %0, t; }"
        : "=r"(a) : "l"(p));
    return a;
}

__device__ __forceinline__ uint32_t pack_bf16(float x, float y) {
    uint32_t r;
    asm("cvt.rn.bf16x2.f32 %0, %1, %2;" : "=r"(r) : "f"(y), "f"(x));
    return r;
}
__device__ __forceinline__ void split2(float x, float y, uint32_t& h, uint32_t& l) {
    h = pack_bf16(x, y);
    float hx = __uint_as_float(h << 16);
    float hy = __uint_as_float(h & 0xffff0000u);
    l = pack_bf16(x - hx, y - hy);
}

__device__ __forceinline__ void ldsm_x4(uint32_t addr, uint32_t& r0,
                                        uint32_t& r1, uint32_t& r2, uint32_t& r3) {
    asm volatile("ldmatrix.sync.aligned.m8n8.x4.shared.b16 {%0,%1,%2,%3}, [%4];"
                 : "=r"(r0), "=r"(r1), "=r"(r2), "=r"(r3) : "r"(addr));
}
__device__ __forceinline__ void ldsm_x4_t(uint32_t addr, uint32_t& r0,
                                          uint32_t& r1, uint32_t& r2, uint32_t& r3) {
    asm volatile("ldmatrix.sync.aligned.m8n8.x4.trans.shared.b16 {%0,%1,%2,%3}, [%4];"
                 : "=r"(r0), "=r"(r1), "=r"(r2), "=r"(r3) : "r"(addr));
}

__device__ __forceinline__ void mma_bf16(float c[4],
                                         uint32_t a0, uint32_t a1,
                                         uint32_t a2, uint32_t a3,
                                         uint32_t b0, uint32_t b1) {
    asm volatile(
        "mma.sync.aligned.m16n8k16.row.col.f32.bf16.bf16.f32 "
        "{%0,%1,%2,%3}, {%4,%5,%6,%7}, {%8,%9}, {%0,%1,%2,%3};"
        : "+f"(c[0]), "+f"(c[1]), "+f"(c[2]), "+f"(c[3])
        : "r"(a0), "r"(a1), "r"(a2), "r"(a3), "r"(b0), "r"(b1));
}

#define CP_ASYNC(dst, src) \
    asm volatile("cp.async.cg.shared.global [%0], [%1], 16;" \
                 :: "r"(dst), "l"(src) : "memory")
#define CP_COMMIT() asm volatile("cp.async.commit_group;" ::: "memory")

// ---------------- init / CSR build -----------------------------------------
__global__ void k_zero() {
    int i = blockIdx.x * blockDim.x + threadIdx.x;
    if (i < NG * HID) g_pool[i] = 0.f;
    if (i < NG)       g_cnt[i]  = 0.f;
    if (i < NN) { g_degi[i] = 0; g_fillcnt[i] = 0; }
}

__global__ void k_deg(const int* __restrict__ ei) {
    int e = blockIdx.x * blockDim.x + threadIdx.x;
    if (e < NE) atomicAdd(&g_degi[ei[NE + e]], 1);
}

__global__ void __launch_bounds__(1024)
k_scan1() {
    __shared__ int ws[32];
    int t    = threadIdx.x;
    int lane = t & 31;
    int w    = t >> 5;
    int i    = blockIdx.x * 1024 + t;
    int d = (i < NN) ? g_degi[i] : 0;
    int v = d;
#pragma unroll
    for (int o = 1; o < 32; o <<= 1) {
        int u = __shfl_up_sync(0xffffffff, v, o);
        if (lane >= o) v += u;
    }
    if (lane == 31) ws[w] = v;
    __syncthreads();
    if (w == 0) {
        int x = ws[lane];
#pragma unroll
        for (int o = 1; o < 32; o <<= 1) {
            int u = __shfl_up_sync(0xffffffff, x, o);
            if (lane >= o) x += u;
        }
        ws[lane] = x;
    }
    __syncthreads();
    int incl = v + (w ? ws[w - 1] : 0);
    if (i < NN) g_rowptr[i] = incl;
    if (t == 1023) g_bsum[blockIdx.x] = incl;
}

__global__ void k_scan2() {
    int lane = threadIdx.x;
    int v0 = (lane < NBLK) ? g_bsum[lane] : 0;
    int v1 = (32 + lane < NBLK) ? g_bsum[32 + lane] : 0;
    int s0 = v0, s1 = v1;
#pragma unroll
    for (int o = 1; o < 32; o <<= 1) {
        int u0 = __shfl_up_sync(0xffffffff, s0, o);
        int u1 = __shfl_up_sync(0xffffffff, s1, o);
        if (lane >= o) { s0 += u0; s1 += u1; }
    }
    int tot0 = __shfl_sync(0xffffffff, s0, 31);
    if (lane < NBLK)      g_bsum[lane]      = s0 - v0;
    if (32 + lane < NBLK) g_bsum[32 + lane] = s1 - v1 + tot0;
}

__global__ void k_scan3() {
    int i = blockIdx.x * blockDim.x + threadIdx.x;
    if (i < NN) {
        int incl = g_rowptr[i];
        int d    = g_degi[i];
        g_rowptr[i] = incl - d + g_bsum[i >> 10];
        g_dinv[i]   = rsqrtf((float)d + 1.f);
    }
    if (i == 0) g_rowptr[NN] = NE;
}

__global__ void k_fill(const int* __restrict__ ei) {
    int e = blockIdx.x * blockDim.x + threadIdx.x;
    if (e >= NE) return;
    int s = ei[e];
    int d = ei[NE + e];
    int pos = g_rowptr[d] + atomicAdd(&g_fillcnt[d], 1);
    g_csr[pos] = s;
}

// ---------------- weight pre-split ------------------------------------------
__global__ void k_wsplit(const float* __restrict__ We2,
                         const float* __restrict__ Wg) {
    int i = blockIdx.x * blockDim.x + threadIdx.x;
    if (i >= 5 * 8192) return;
    int mat = i >> 13;
    int off = i & 8191;
    const float* src = (mat == 0) ? (We2 + off * 2)
                                  : (Wg + (mat - 1) * 16384 + off * 2);
    uint32_t h, l;
    split2(src[0], src[1], h, l);
    g_Wh[i] = h;
    g_Wl[i] = l;
}

// ---------------- embed layer 1: 4 nodes per thread -------------------------
__global__ void __launch_bounds__(256)
k_embed1(const float* __restrict__ x,
         const float* __restrict__ W,
         const float* __restrict__ b) {
    __shared__ float Ws[FEAT][HID];
    __shared__ float xs[64][FEAT + 1];

    const int tid = threadIdx.x;
    const int n0  = blockIdx.x * 64;

    {
        const float4* Wv = reinterpret_cast<const float4*>(W);
        float4* Wsv = reinterpret_cast<float4*>(&Ws[0][0]);
        Wsv[tid]       = Wv[tid];
        Wsv[tid + 256] = Wv[tid + 256];
    }
    {
        int node = n0 + (tid >> 2);
        float4 v = make_float4(0.f, 0.f, 0.f, 0.f);
        if (node < NN)
            v = reinterpret_cast<const float4*>(x)[node * 4 + (tid & 3)];
        int li = tid >> 2, q = tid & 3;
        xs[li][q * 4 + 0] = v.x;
        xs[li][q * 4 + 1] = v.y;
        xs[li][q * 4 + 2] = v.z;
        xs[li][q * 4 + 3] = v.w;
    }
    __syncthreads();

    const int rg = tid >> 4;
    const int cg = tid & 15;
    float acc[4][8];
    float bb[8];
#pragma unroll
    for (int j = 0; j < 8; j++) bb[j] = b[cg * 8 + j];
#pragma unroll
    for (int v = 0; v < 4; v++)
#pragma unroll
        for (int j = 0; j < 8; j++) acc[v][j] = bb[j];

#pragma unroll
    for (int k = 0; k < FEAT; k++) {
        float4 w0 = *reinterpret_cast<const float4*>(&Ws[k][cg * 8]);
        float4 w1 = *reinterpret_cast<const float4*>(&Ws[k][cg * 8 + 4]);
#pragma unroll
        for (int v = 0; v < 4; v++) {
            float xv = xs[rg * 4 + v][k];
            acc[v][0] += xv * w0.x; acc[v][1] += xv * w0.y;
            acc[v][2] += xv * w0.z; acc[v][3] += xv * w0.w;
            acc[v][4] += xv * w1.x; acc[v][5] += xv * w1.y;
            acc[v][6] += xv * w1.z; acc[v][7] += xv * w1.w;
        }
    }
#pragma unroll
    for (int v = 0; v < 4; v++) {
        int node = n0 + rg * 4 + v;
        if (node >= NN) continue;
        uint32_t h[4], l[4];
#pragma unroll
        for (int q = 0; q < 4; q++)
            split2(fmaxf(acc[v][2 * q], 0.f), fmaxf(acc[v][2 * q + 1], 0.f),
                   h[q], l[q]);
        reinterpret_cast<uint4*>(g_A0h)[node * 16 + cg] =
            make_uint4(h[0], h[1], h[2], h[3]);
        reinterpret_cast<uint4*>(g_A0l)[node * 16 + cg] =
            make_uint4(l[0], l[1], l[2], l[3]);
    }
}

// ---------------- bf16-split tensor GEMM (global split-A input) -------------
__global__ void __launch_bounds__(256, 2)
k_gemm_bf(const uint32_t* __restrict__ Ah, const uint32_t* __restrict__ Al,
          const uint32_t* __restrict__ Wh, const uint32_t* __restrict__ Wl,
          const float* __restrict__ bias,
          uint32_t* __restrict__ Cfh,
          uint32_t* __restrict__ Ch, uint32_t* __restrict__ Cl,
          int N) {
    __shared__ __align__(16) uint32_t       sA[2][2][128][APITCH];
    __shared__ __align__(16) unsigned short sB[2][2][16][BPITCH];

    const int tid  = threadIdx.x;
    const int wid  = tid >> 5;
    const int lane = tid & 31;
    const int grp  = lane >> 2;
    const int tig  = lane & 3;
    const int row0 = blockIdx.x * 128;
    const int wm   = wid * 16;

    const int b_rf = ((lane >> 3) & 1) * 8 + (lane & 7);
    const int b_c8 = (lane >> 4) * 8;
    const int a_r  = wm + (lane & 15);
    const int a_c4 = (lane >> 4) * 4;

    float c[16][4];
#pragma unroll
    for (int i = 0; i < 16; i++)
#pragma unroll
        for (int j = 0; j < 4; j++) c[i][j] = 0.f;

    auto issue = [&](int kc) {
        int s = kc & 1;
        {
            int r = tid >> 1, q = tid & 1;
            long src = (long)min(row0 + r, N - 1) * 64 + kc * 8 + q * 4;
            CP_ASYNC(smem_u32(&sA[s][0][r][q * 4]), Ah + src);
            CP_ASYNC(smem_u32(&sA[s][1][r][q * 4]), Al + src);
        }
        {
            int r = tid >> 4, cu = tid & 15;
            long src = (long)(kc * 16 + r) * 64 + cu * 4;
            CP_ASYNC(smem_u32(&sB[s][0][r][cu * 8]), Wh + src);
            CP_ASYNC(smem_u32(&sB[s][1][r][cu * 8]), Wl + src);
        }
        CP_COMMIT();
    };

    issue(0);

    for (int kc = 0; kc < 8; kc++) {
        if (kc < 7) {
            issue(kc + 1);
            asm volatile("cp.async.wait_group 1;" ::: "memory");
        } else {
            asm volatile("cp.async.wait_group 0;" ::: "memory");
        }
        __syncthreads();

        const int s = kc & 1;
        uint32_t ah0, ah1, ah2, ah3, al0, al1, al2, al3;
        ldsm_x4(smem_u32(&sA[s][0][a_r][a_c4]), ah0, ah1, ah2, ah3);
        ldsm_x4(smem_u32(&sA[s][1][a_r][a_c4]), al0, al1, al2, al3);

#pragma unroll
        for (int np = 0; np < 8; np++) {
            uint32_t bh0, bh1, bh2, bh3, bl0, bl1, bl2, bl3;
            ldsm_x4_t(smem_u32(&sB[s][0][b_rf][np * 16 + b_c8]),
                      bh0, bh1, bh2, bh3);
            ldsm_x4_t(smem_u32(&sB[s][1][b_rf][np * 16 + b_c8]),
                      bl0, bl1, bl2, bl3);
            mma_bf16(c[2 * np],     ah0, ah1, ah2, ah3, bl0, bl1);
            mma_bf16(c[2 * np],     al0, al1, al2, al3, bh0, bh1);
            mma_bf16(c[2 * np],     ah0, ah1, ah2, ah3, bh0, bh1);
            mma_bf16(c[2 * np + 1], ah0, ah1, ah2, ah3, bl2, bl3);
            mma_bf16(c[2 * np + 1], al0, al1, al2, al3, bh2, bh3);
            mma_bf16(c[2 * np + 1], ah0, ah1, ah2, ah3, bh2, bh3);
        }
        if (kc < 7) __syncthreads();
    }

    const int r_lo = row0 + wm + grp;
    const int r_hi = r_lo + 8;
#pragma unroll
    for (int nt = 0; nt < 16; nt++) {
        int col = nt * 8 + 2 * tig;
        float2 v0 = make_float2(c[nt][0], c[nt][1]);
        float2 v1 = make_float2(c[nt][2], c[nt][3]);
        if (bias) {
            float2 bb = *reinterpret_cast<const float2*>(&bias[col]);
            v0.x += bb.x; v0.y += bb.y;
            v1.x += bb.x; v1.y += bb.y;
        }
        int ci = nt * 4 + tig;
        if (Cfh) {
            __half2 p0 = __floats2half2_rn(v0.x, v0.y);
            __half2 p1 = __floats2half2_rn(v1.x, v1.y);
            if (r_lo < N) Cfh[r_lo * 64 + ci] = *reinterpret_cast<uint32_t*>(&p0);
            if (r_hi < N) Cfh[r_hi * 64 + ci] = *reinterpret_cast<uint32_t*>(&p1);
        } else {
            uint32_t h0, l0, h1, l1;
            split2(v0.x, v0.y, h0, l0);
            split2(v1.x, v1.y, h1, l1);
            if (r_lo < N) { Ch[r_lo * 64 + ci] = h0; Cl[r_lo * 64 + ci] = l0; }
            if (r_hi < N) { Ch[r_hi * 64 + ci] = h1; Cl[r_hi * 64 + ci] = l1; }
        }
    }
}

// ---------------- FUSED: spmm(layer i) -> smem split A -> gemm(W_{i+1}) -----
// Block owns 128 nodes. Phase 1: each warp spmm-gathers 16 rows from hwin,
// relu+bias, bf16-splits straight into the A tile (272B rows, LDSM-safe).
// Phase 2: proven HMMA loop, B via cp.async, output half2 to hwout.
__global__ void __launch_bounds__(256, 2)
k_fused(const uint32_t* __restrict__ hwin,
        const uint32_t* __restrict__ Wh, const uint32_t* __restrict__ Wl,
        const float* __restrict__ bias,
        uint32_t* __restrict__ hwout) {
    __shared__ __align__(16) uint32_t       sAh[128][FPITCH];
    __shared__ __align__(16) uint32_t       sAl[128][FPITCH];
    __shared__ __align__(16) unsigned short sB[2][2][16][BPITCH];

    const int tid  = threadIdx.x;
    const int wid  = tid >> 5;
    const int lane = tid & 31;
    const int grp  = lane >> 2;
    const int tig  = lane & 3;
    const int row0 = blockIdx.x * 128;
    const int wm   = wid * 16;

    // ---- phase 1: spmm for rows wm..wm+15 of this tile ----
    const uint2* hw2 = reinterpret_cast<const uint2*>(hwin);
    float4 bb4 = reinterpret_cast<const float4*>(bias)[lane];

    for (int t = 0; t < 16; t++) {
        int r = wm + t;
        int n = row0 + r;
        float4 acc = make_float4(0.f, 0.f, 0.f, 0.f);
        if (n < NN) {
            float dn = g_dinv[n];
            int start = g_rowptr[n];
            int end   = g_rowptr[n + 1];
            {   // self-loop
                uint2 u = hw2[(long)n * 32 + lane];
                float2 f0 = __half22float2(*reinterpret_cast<__half2*>(&u.x));
                float2 f1 = __half22float2(*reinterpret_cast<__half2*>(&u.y));
                float d2 = dn * dn;
                acc = make_float4(f0.x * d2, f0.y * d2, f1.x * d2, f1.y * d2);
            }
            for (int base = start; base < end; base += 32) {
                int idx = base + lane;
                int s   = 0;
                float dv = 0.f;
                if (idx < end) {
                    s  = g_csr[idx];
                    dv = g_dinv[s] * dn;
                }
                int m = min(32, end - base);
                for (int j = 0; j < m; j += 4) {
                    int   s0 = __shfl_sync(0xffffffff, s,  j);
                    int   s1 = __shfl_sync(0xffffffff, s,  j + 1);
                    int   s2 = __shfl_sync(0xffffffff, s,  j + 2);
                    int   s3 = __shfl_sync(0xffffffff, s,  j + 3);
                    float n0 = __shfl_sync(0xffffffff, dv, j);
                    float n1 = __shfl_sync(0xffffffff, dv, j + 1);
                    float n2 = __shfl_sync(0xffffffff, dv, j + 2);
                    float n3 = __shfl_sync(0xffffffff, dv, j + 3);
                    uint2 u0 = hw2[(long)s0 * 32 + lane];
                    uint2 u1 = hw2[(long)s1 * 32 + lane];
                    uint2 u2 = hw2[(long)s2 * 32 + lane];
                    uint2 u3 = hw2[(long)s3 * 32 + lane];
                    float2 a0 = __half22float2(*reinterpret_cast<__half2*>(&u0.x));
                    float2 b0 = __half22float2(*reinterpret_cast<__half2*>(&u0.y));
                    float2 a1 = __half22float2(*reinterpret_cast<__half2*>(&u1.x));
                    float2 b1 = __half22float2(*reinterpret_cast<__half2*>(&u1.y));
                    float2 a2 = __half22float2(*reinterpret_cast<__half2*>(&u2.x));
                    float2 b2 = __half22float2(*reinterpret_cast<__half2*>(&u2.y));
                    float2 a3 = __half22float2(*reinterpret_cast<__half2*>(&u3.x));
                    float2 b3 = __half22float2(*reinterpret_cast<__half2*>(&u3.y));
                    acc.x += a0.x * n0; acc.y += a0.y * n0;
                    acc.z += b0.x * n0; acc.w += b0.y * n0;
                    acc.x += a1.x * n1; acc.y += a1.y * n1;
                    acc.z += b1.x * n1; acc.w += b1.y * n1;
                    acc.x += a2.x * n2; acc.y += a2.y * n2;
                    acc.z += b2.x * n2; acc.w += b2.y * n2;
                    acc.x += a3.x * n3; acc.y += a3.y * n3;
                    acc.z += b3.x * n3; acc.w += b3.y * n3;
                }
            }
            acc.x = fmaxf(acc.x + bb4.x, 0.f);
            acc.y = fmaxf(acc.y + bb4.y, 0.f);
            acc.z = fmaxf(acc.z + bb4.z, 0.f);
            acc.w = fmaxf(acc.w + bb4.w, 0.f);
        }
        uint32_t h01, l01, h23, l23;
        split2(acc.x, acc.y, h01, l01);
        split2(acc.z, acc.w, h23, l23);
        sAh[r][2 * lane]     = h01;
        sAh[r][2 * lane + 1] = h23;
        sAl[r][2 * lane]     = l01;
        sAl[r][2 * lane + 1] = l23;
    }
    __syncthreads();

    // ---- phase 2: gemm from smem A, cp.async B ----
    const int b_rf = ((lane >> 3) & 1) * 8 + (lane & 7);
    const int b_c8 = (lane >> 4) * 8;
    const int a_r  = wm + (lane & 15);
    const int a_c4 = (lane >> 4) * 4;

    float c[16][4];
#pragma unroll
    for (int i = 0; i < 16; i++)
#pragma unroll
        for (int j = 0; j < 4; j++) c[i][j] = 0.f;

    auto issueB = [&](int kc) {
        int s = kc & 1;
        int r = tid >> 4, cu = tid & 15;
        long src = (long)(kc * 16 + r) * 64 + cu * 4;
        CP_ASYNC(smem_u32(&sB[s][0][r][cu * 8]), Wh + src);
        CP_ASYNC(smem_u32(&sB[s][1][r][cu * 8]), Wl + src);
        CP_COMMIT();
    };

    issueB(0);

    for (int kc = 0; kc < 8; kc++) {
        if (kc < 7) {
            issueB(kc + 1);
            asm volatile("cp.async.wait_group 1;" ::: "memory");
        } else {
            asm volatile("cp.async.wait_group 0;" ::: "memory");
        }
        __syncthreads();

        const int s = kc & 1;
        uint32_t ah0, ah1, ah2, ah3, al0, al1, al2, al3;
        ldsm_x4(smem_u32(&sAh[a_r][kc * 8 + a_c4]), ah0, ah1, ah2, ah3);
        ldsm_x4(smem_u32(&sAl[a_r][kc * 8 + a_c4]), al0, al1, al2, al3);

#pragma unroll
        for (int np = 0; np < 8; np++) {
            uint32_t bh0, bh1, bh2, bh3, bl0, bl1, bl2, bl3;
            ldsm_x4_t(smem_u32(&sB[s][0][b_rf][np * 16 + b_c8]),
                      bh0, bh1, bh2, bh3);
            ldsm_x4_t(smem_u32(&sB[s][1][b_rf][np * 16 + b_c8]),
                      bl0, bl1, bl2, bl3);
            mma_bf16(c[2 * np],     ah0, ah1, ah2, ah3, bl0, bl1);
            mma_bf16(c[2 * np],     al0, al1, al2, al3, bh0, bh1);
            mma_bf16(c[2 * np],     ah0, ah1, ah2, ah3, bh0, bh1);
            mma_bf16(c[2 * np + 1], ah0, ah1, ah2, ah3, bl2, bl3);
            mma_bf16(c[2 * np + 1], al0, al1, al2, al3, bh2, bh3);
            mma_bf16(c[2 * np + 1], ah0, ah1, ah2, ah3, bh2, bh3);
        }
        if (kc < 7) __syncthreads();
    }

    const int r_lo = row0 + wm + grp;
    const int r_hi = r_lo + 8;
#pragma unroll
    for (int nt = 0; nt < 16; nt++) {
        int ci = nt * 4 + tig;
        __half2 p0 = __floats2half2_rn(c[nt][0], c[nt][1]);
        __half2 p1 = __floats2half2_rn(c[nt][2], c[nt][3]);
        if (r_lo < NN) hwout[r_lo * 64 + ci] = *reinterpret_cast<uint32_t*>(&p0);
        if (r_hi < NN) hwout[r_hi * 64 + ci] = *reinterpret_cast<uint32_t*>(&p1);
    }
}

// ---------------- final-layer SpMM + pooling ---------------------------------
__global__ void __launch_bounds__(256)
k_spmm(const uint32_t* __restrict__ hwf,
       const float* __restrict__ bias, const int* __restrict__ bidx) {
    int gt = blockIdx.x * blockDim.x + threadIdx.x;
    int n  = gt >> 5;
    int l  = gt & 31;
    if (n >= NN) return;

    const uint2* hw2 = reinterpret_cast<const uint2*>(hwf);
    float dn = g_dinv[n];
    int start = g_rowptr[n];
    int end   = g_rowptr[n + 1];

    float4 acc;
    {
        uint2 u = hw2[(long)n * 32 + l];
        float2 f0 = __half22float2(*reinterpret_cast<__half2*>(&u.x));
        float2 f1 = __half22float2(*reinterpret_cast<__half2*>(&u.y));
        float d2 = dn * dn;
        acc = make_float4(f0.x * d2, f0.y * d2, f1.x * d2, f1.y * d2);
    }

    for (int base = start; base < end; base += 32) {
        int idx = base + l;
        int s   = 0;
        float dv = 0.f;
        if (idx < end) {
            s  = g_csr[idx];
            dv = g_dinv[s] * dn;
        }
        int m = min(32, end - base);
        for (int j = 0; j < m; j += 4) {
            int   s0 = __shfl_sync(0xffffffff, s,  j);
            int   s1 = __shfl_sync(0xffffffff, s,  j + 1);
            int   s2 = __shfl_sync(0xffffffff, s,  j + 2);
            int   s3 = __shfl_sync(0xffffffff, s,  j + 3);
            float n0 = __shfl_sync(0xffffffff, dv, j);
            float n1 = __shfl_sync(0xffffffff, dv, j + 1);
            float n2 = __shfl_sync(0xffffffff, dv, j + 2);
            float n3 = __shfl_sync(0xffffffff, dv, j + 3);
            uint2 u0 = hw2[(long)s0 * 32 + l];
            uint2 u1 = hw2[(long)s1 * 32 + l];
            uint2 u2 = hw2[(long)s2 * 32 + l];
            uint2 u3 = hw2[(long)s3 * 32 + l];
            float2 a0 = __half22float2(*reinterpret_cast<__half2*>(&u0.x));
            float2 b0 = __half22float2(*reinterpret_cast<__half2*>(&u0.y));
            float2 a1 = __half22float2(*reinterpret_cast<__half2*>(&u1.x));
            float2 b1 = __half22float2(*reinterpret_cast<__half2*>(&u1.y));
            float2 a2 = __half22float2(*reinterpret_cast<__half2*>(&u2.x));
            float2 b2 = __half22float2(*reinterpret_cast<__half2*>(&u2.y));
            float2 a3 = __half22float2(*reinterpret_cast<__half2*>(&u3.x));
            float2 b3 = __half22float2(*reinterpret_cast<__half2*>(&u3.y));
            acc.x += a0.x * n0; acc.y += a0.y * n0;
            acc.z += b0.x * n0; acc.w += b0.y * n0;
            acc.x += a1.x * n1; acc.y += a1.y * n1;
            acc.z += b1.x * n1; acc.w += b1.y * n1;
            acc.x += a2.x * n2; acc.y += a2.y * n2;
            acc.z += b2.x * n2; acc.w += b2.y * n2;
            acc.x += a3.x * n3; acc.y += a3.y * n3;
            acc.z += b3.x * n3; acc.w += b3.y * n3;
        }
    }

    float4 bb = reinterpret_cast<const float4*>(bias)[l];
    acc.x = fmaxf(acc.x + bb.x, 0.f);
    acc.y = fmaxf(acc.y + bb.y, 0.f);
    acc.z = fmaxf(acc.z + bb.z, 0.f);
    acc.w = fmaxf(acc.w + bb.w, 0.f);

    int g = bidx[n];
    red_add_f4(&g_pool[g * HID + l * 4], acc);
    if (l == 0) atomicAdd(&g_cnt[g], 1.f);
}

// ---------------- output head ------------------------------------------------
__global__ void k_out(const float* __restrict__ Wo,
                      const float* __restrict__ bo,
                      float* __restrict__ out) {
    int t = blockIdx.x * blockDim.x + threadIdx.x;
    if (t >= NG * OD) return;
    int g = t / OD;
    int o = t % OD;
    float inv = 1.f / fmaxf(g_cnt[g], 1.f);
    float acc = 0.f;
#pragma unroll 8
    for (int k = 0; k < HID; k++)
        acc += g_pool[g * HID + k] * Wo[k * OD + o];
    out[t] = acc * inv + bo[o];
}

// ---------------- launch: fork-join + fused layers ---------------------------
extern "C" void kernel_launch(void* const* d_in, const int* in_sizes, int n_in,
                              void* d_out, int out_size) {
    const float* x    = (const float*)d_in[0];
    const int*   ei   = (const int*)d_in[1];
    const int*   bidx = (const int*)d_in[3];
    const float* We1  = (const float*)d_in[4];
    const float* be1  = (const float*)d_in[5];
    const float* We2  = (const float*)d_in[6];
    const float* be2  = (const float*)d_in[7];
    const float* Wg   = (const float*)d_in[8];
    const float* bg   = (const float*)d_in[9];
    const float* Wo   = (const float*)d_in[10];
    const float* bo   = (const float*)d_in[11];
    float*       out  = (float*)d_out;

    uint32_t *phw0, *phw1, *pA0h, *pA0l, *pA1h, *pA1l, *pWh, *pWl;
    cudaGetSymbolAddress((void**)&phw0, g_hwf0);
    cudaGetSymbolAddress((void**)&phw1, g_hwf1);
    cudaGetSymbolAddress((void**)&pA0h, g_A0h);
    cudaGetSymbolAddress((void**)&pA0l, g_A0l);
    cudaGetSymbolAddress((void**)&pA1h, g_A1h);
    cudaGetSymbolAddress((void**)&pA1l, g_A1l);
    cudaGetSymbolAddress((void**)&pWh,  g_Wh);
    cudaGetSymbolAddress((void**)&pWl,  g_Wl);

    const int TB = 256;
    const int GB = (NN + 127) / 128;        // 391
    cudaStream_t s2 = g_hx.s2;

    // fork
    cudaEventRecord(g_hx.eFork, 0);
    cudaStreamWaitEvent(s2, g_hx.eFork, 0);

    // s2: weight pre-split, then CSR build chain
    k_wsplit<<<160, TB, 0, s2>>>(We2, Wg);
    cudaEventRecord(g_hx.eW, s2);
    k_zero <<<(NG * HID + TB - 1) / TB, TB, 0, s2>>>();
    k_deg  <<<(NE + TB - 1) / TB, TB, 0, s2>>>(ei);
    k_scan1<<<NBLK, 1024, 0, s2>>>();
    k_scan2<<<1, 32, 0, s2>>>();
    k_scan3<<<(NN + TB - 1) / TB, TB, 0, s2>>>();
    k_fill <<<(NE + TB - 1) / TB, TB, 0, s2>>>(ei);
    cudaEventRecord(g_hx.eCsr, s2);

    // s0: embed1 -> G0 (embed2, split out) -> G1 (layer-1 gemm, half2 out)
    k_embed1<<<(NN + 63) / 64, TB>>>(x, We1, be1);
    cudaStreamWaitEvent(0, g_hx.eW, 0);
    k_gemm_bf<<<GB, TB>>>(pA0h, pA0l, pWh, pWl, be2,
                          nullptr, pA1h, pA1l, NN);
    k_gemm_bf<<<GB, TB>>>(pA1h, pA1l, pWh + 8192, pWl + 8192, nullptr,
                          phw0, nullptr, nullptr, NN);

    // fused layers: F_i = spmm(layer i) + gemm(W_{i+1})
    cudaStreamWaitEvent(0, g_hx.eCsr, 0);
    k_fused<<<GB, TB>>>(phw0, pWh + 2 * 8192, pWl + 2 * 8192, bg + 0 * HID, phw1);
    k_fused<<<GB, TB>>>(phw1, pWh + 3 * 8192, pWl + 3 * 8192, bg + 1 * HID, phw0);
    k_fused<<<GB, TB>>>(phw0, pWh + 4 * 8192, pWl + 4 * 8192, bg + 2 * HID, phw1);

    // final layer: spmm + pooling, then head
    k_spmm<<<(NN * 32 + TB - 1) / TB, TB>>>(phw1, bg + 3 * HID, bidx);
    k_out<<<(NG * OD + TB - 1) / TB, TB>>>(Wo, bo, out);
}

// round 15
// speedup vs baseline: 1.3651x; 1.3651x over previous
#include <cuda_runtime.h>
#include <cuda_bf16.h>
#include <cuda_fp16.h>
#include <cstdint>

#define NN   50000
#define NE   800000
#define FEAT 16
#define HID  128
#define NL   4
#define NG   1024
#define OD   12
#define NBLK ((NN + 1023) / 1024)
#define BPITCH 136     // ushorts: 272B rows, LDSM.trans conflict-free (proven)
#define APITCH 12      // uint32:  48B rows (gemm A stage, proven)
#define FPITCH 68      // uint32:  272B rows for fused A tile (proven R14)

// ---------------- streams / events: created at program load -----------------
struct HxStreams {
    cudaStream_t s1, s2;
    cudaEvent_t  eFork, eW, eCsr;
    HxStreams() {
        cudaStreamCreateWithFlags(&s1, cudaStreamNonBlocking);
        cudaStreamCreateWithFlags(&s2, cudaStreamNonBlocking);
        cudaEventCreateWithFlags(&eFork, cudaEventDisableTiming);
        cudaEventCreateWithFlags(&eW,    cudaEventDisableTiming);
        cudaEventCreateWithFlags(&eCsr,  cudaEventDisableTiming);
    }
};
static HxStreams g_hx;

// ---------------- scratch (device globals) ----------------------------------
__device__ uint32_t g_hwf[NN * 64];        // half2-packed GEMM out (spmm input)
__device__ uint32_t g_A1h[NN * 64];        // split bf16 activations
__device__ uint32_t g_A1l[NN * 64];
__device__ uint32_t g_Wh[5 * 8192];
__device__ uint32_t g_Wl[5 * 8192];
__device__ float    g_dinv[NN];
__device__ float    g_pool[NG * HID];
__device__ float    g_cnt[NG];
__device__ int      g_degi[NN];
__device__ int      g_rowptr[NN + 1];
__device__ int      g_fillcnt[NN];
__device__ int      g_csr[NE];
__device__ int      g_bsum[64];

__device__ __forceinline__ void red_add_f4(float* p, float4 v) {
    asm volatile("red.global.add.v4.f32 [%0], {%1,%2,%3,%4};"
                 :: "l"(p), "f"(v.x), "f"(v.y), "f"(v.z), "f"(v.w)
                 : "memory");
}

__device__ __forceinline__ uint32_t smem_u32(const void* p) {
    uint32_t a;
    asm("{ .reg .u64 t; cvta.to.shared.u64 t, %1; cvt.u32.u64 %0, t; }"
        : "=r"(a) : "l"(p));
    return a;
}

__device__ __forceinline__ uint32_t pack_bf16(float x, float y) {
    uint32_t r;
    asm("cvt.rn.bf16x2.f32 %0, %1, %2;" : "=r"(r) : "f"(y), "f"(x));
    return r;
}
__device__ __forceinline__ void split2(float x, float y, uint32_t& h, uint32_t& l) {
    h = pack_bf16(x, y);
    float hx = __uint_as_float(h << 16);
    float hy = __uint_as_float(h & 0xffff0000u);
    l = pack_bf16(x - hx, y - hy);
}

__device__ __forceinline__ void ldsm_x4(uint32_t addr, uint32_t& r0,
                                        uint32_t& r1, uint32_t& r2, uint32_t& r3) {
    asm volatile("ldmatrix.sync.aligned.m8n8.x4.shared.b16 {%0,%1,%2,%3}, [%4];"
                 : "=r"(r0), "=r"(r1), "=r"(r2), "=r"(r3) : "r"(addr));
}
__device__ __forceinline__ void ldsm_x4_t(uint32_t addr, uint32_t& r0,
                                          uint32_t& r1, uint32_t& r2, uint32_t& r3) {
    asm volatile("ldmatrix.sync.aligned.m8n8.x4.trans.shared.b16 {%0,%1,%2,%3}, [%4];"
                 : "=r"(r0), "=r"(r1), "=r"(r2), "=r"(r3) : "r"(addr));
}

__device__ __forceinline__ void mma_bf16(float c[4],
                                         uint32_t a0, uint32_t a1,
                                         uint32_t a2, uint32_t a3,
                                         uint32_t b0, uint32_t b1) {
    asm volatile(
        "mma.sync.aligned.m16n8k16.row.col.f32.bf16.bf16.f32 "
        "{%0,%1,%2,%3}, {%4,%5,%6,%7}, {%8,%9}, {%0,%1,%2,%3};"
        : "+f"(c[0]), "+f"(c[1]), "+f"(c[2]), "+f"(c[3])
        : "r"(a0), "r"(a1), "r"(a2), "r"(a3), "r"(b0), "r"(b1));
}

#define CP_ASYNC(dst, src) \
    asm volatile("cp.async.cg.shared.global [%0], [%1], 16;" \
                 :: "r"(dst), "l"(src) : "memory")
#define CP_COMMIT() asm volatile("cp.async.commit_group;" ::: "memory")

// ---------------- init / CSR build -----------------------------------------
__global__ void k_zero() {
    int i = blockIdx.x * blockDim.x + threadIdx.x;
    if (i < NG * HID) g_pool[i] = 0.f;
    if (i < NG)       g_cnt[i]  = 0.f;
    if (i < NN) { g_degi[i] = 0; g_fillcnt[i] = 0; }
}

__global__ void k_deg(const int* __restrict__ ei) {
    int e = blockIdx.x * blockDim.x + threadIdx.x;
    if (e < NE) atomicAdd(&g_degi[ei[NE + e]], 1);
}

__global__ void __launch_bounds__(1024)
k_scan1() {
    __shared__ int ws[32];
    int t    = threadIdx.x;
    int lane = t & 31;
    int w    = t >> 5;
    int i    = blockIdx.x * 1024 + t;
    int d = (i < NN) ? g_degi[i] : 0;
    int v = d;
#pragma unroll
    for (int o = 1; o < 32; o <<= 1) {
        int u = __shfl_up_sync(0xffffffff, v, o);
        if (lane >= o) v += u;
    }
    if (lane == 31) ws[w] = v;
    __syncthreads();
    if (w == 0) {
        int x = ws[lane];
#pragma unroll
        for (int o = 1; o < 32; o <<= 1) {
            int u = __shfl_up_sync(0xffffffff, x, o);
            if (lane >= o) x += u;
        }
        ws[lane] = x;
    }
    __syncthreads();
    int incl = v + (w ? ws[w - 1] : 0);
    if (i < NN) g_rowptr[i] = incl;
    if (t == 1023) g_bsum[blockIdx.x] = incl;
}

__global__ void k_scan2() {
    int lane = threadIdx.x;
    int v0 = (lane < NBLK) ? g_bsum[lane] : 0;
    int v1 = (32 + lane < NBLK) ? g_bsum[32 + lane] : 0;
    int s0 = v0, s1 = v1;
#pragma unroll
    for (int o = 1; o < 32; o <<= 1) {
        int u0 = __shfl_up_sync(0xffffffff, s0, o);
        int u1 = __shfl_up_sync(0xffffffff, s1, o);
        if (lane >= o) { s0 += u0; s1 += u1; }
    }
    int tot0 = __shfl_sync(0xffffffff, s0, 31);
    if (lane < NBLK)      g_bsum[lane]      = s0 - v0;
    if (32 + lane < NBLK) g_bsum[32 + lane] = s1 - v1 + tot0;
}

__global__ void k_scan3() {
    int i = blockIdx.x * blockDim.x + threadIdx.x;
    if (i < NN) {
        int incl = g_rowptr[i];
        int d    = g_degi[i];
        g_rowptr[i] = incl - d + g_bsum[i >> 10];
        g_dinv[i]   = rsqrtf((float)d + 1.f);
    }
    if (i == 0) g_rowptr[NN] = NE;
}

__global__ void k_fill(const int* __restrict__ ei) {
    int e = blockIdx.x * blockDim.x + threadIdx.x;
    if (e >= NE) return;
    int s = ei[e];
    int d = ei[NE + e];
    int pos = g_rowptr[d] + atomicAdd(&g_fillcnt[d], 1);
    g_csr[pos] = s;
}

// ---------------- weight pre-split ------------------------------------------
__global__ void k_wsplit(const float* __restrict__ We2,
                         const float* __restrict__ Wg) {
    int i = blockIdx.x * blockDim.x + threadIdx.x;
    if (i >= 5 * 8192) return;
    int mat = i >> 13;
    int off = i & 8191;
    const float* src = (mat == 0) ? (We2 + off * 2)
                                  : (Wg + (mat - 1) * 16384 + off * 2);
    uint32_t h, l;
    split2(src[0], src[1], h, l);
    g_Wh[i] = h;
    g_Wl[i] = l;
}

// ---------------- FUSED embed: A1 = (relu(x@We1+be1)) @ We2 + be2 (split) ---
// Block owns 128 nodes. Phase 1: dense K=16 embed into smem split-A tile.
// Phase 2: proven HMMA loop with We2 (cp.async), split-bf16 epilogue -> A1.
// Phase-1 staging (Ws+xs) is smem-aliased with phase-2 B buffers.
__global__ void __launch_bounds__(256, 2)
k_embed_gemm(const float* __restrict__ x,
             const float* __restrict__ We1, const float* __restrict__ be1,
             const uint32_t* __restrict__ Wh, const uint32_t* __restrict__ Wl,
             const float* __restrict__ be2,
             uint32_t* __restrict__ Ch, uint32_t* __restrict__ Cl) {
    __shared__ __align__(16) uint32_t sAh[128][FPITCH];   // 34816 B
    __shared__ __align__(16) uint32_t sAl[128][FPITCH];   // 34816 B
    __shared__ __align__(16) char     sMix[17408];        // Ws+xs | sB

    float (*Ws)[HID]     = reinterpret_cast<float(*)[HID]>(sMix);          // 8192B
    float (*xs)[FEAT+1]  = reinterpret_cast<float(*)[FEAT+1]>(sMix + 8192);// 8704B
    typedef unsigned short (*SBt)[2][16][BPITCH];
    SBt sB = reinterpret_cast<SBt>(sMix);                                  // 17408B

    const int tid  = threadIdx.x;
    const int wid  = tid >> 5;
    const int lane = tid & 31;
    const int grp  = lane >> 2;
    const int tig  = lane & 3;
    const int row0 = blockIdx.x * 128;
    const int wm   = wid * 16;

    // ---- phase 1: embed 128 nodes ----
    {
        const float4* Wv = reinterpret_cast<const float4*>(We1);
        float4* Wsv = reinterpret_cast<float4*>(&Ws[0][0]);
        Wsv[tid]       = Wv[tid];
        Wsv[tid + 256] = Wv[tid + 256];
    }
#pragma unroll
    for (int p = 0; p < 2; p++) {
        int u    = tid + p * 256;           // 0..511
        int node = row0 + (u >> 2);
        float4 v = make_float4(0.f, 0.f, 0.f, 0.f);
        if (node < NN)
            v = reinterpret_cast<const float4*>(x)[node * 4 + (u & 3)];
        int li = u >> 2, q = u & 3;
        xs[li][q * 4 + 0] = v.x;
        xs[li][q * 4 + 1] = v.y;
        xs[li][q * 4 + 2] = v.z;
        xs[li][q * 4 + 3] = v.w;
    }
    __syncthreads();

    {
        const int rg = tid >> 4;            // 8 nodes each
        const int cg = tid & 15;            // 8 cols each
        float acc[8][8];
        float bb[8];
#pragma unroll
        for (int j = 0; j < 8; j++) bb[j] = be1[cg * 8 + j];
#pragma unroll
        for (int v = 0; v < 8; v++)
#pragma unroll
            for (int j = 0; j < 8; j++) acc[v][j] = bb[j];

#pragma unroll
        for (int k = 0; k < FEAT; k++) {
            float4 w0 = *reinterpret_cast<const float4*>(&Ws[k][cg * 8]);
            float4 w1 = *reinterpret_cast<const float4*>(&Ws[k][cg * 8 + 4]);
#pragma unroll
            for (int v = 0; v < 8; v++) {
                float xv = xs[rg * 8 + v][k];
                acc[v][0] += xv * w0.x; acc[v][1] += xv * w0.y;
                acc[v][2] += xv * w0.z; acc[v][3] += xv * w0.w;
                acc[v][4] += xv * w1.x; acc[v][5] += xv * w1.y;
                acc[v][6] += xv * w1.z; acc[v][7] += xv * w1.w;
            }
        }
        __syncthreads();   // done reading Ws/xs before sB overwrite & sA write order
#pragma unroll
        for (int v = 0; v < 8; v++) {
            int r = rg * 8 + v;
#pragma unroll
            for (int q = 0; q < 4; q++) {
                uint32_t h, l;
                split2(fmaxf(acc[v][2 * q], 0.f), fmaxf(acc[v][2 * q + 1], 0.f),
                       h, l);
                sAh[r][cg * 4 + q] = h;
                sAl[r][cg * 4 + q] = l;
            }
        }
    }
    __syncthreads();

    // ---- phase 2: gemm with We2 from smem A, cp.async B ----
    const int b_rf = ((lane >> 3) & 1) * 8 + (lane & 7);
    const int b_c8 = (lane >> 4) * 8;
    const int a_r  = wm + (lane & 15);
    const int a_c4 = (lane >> 4) * 4;

    float c[16][4];
#pragma unroll
    for (int i = 0; i < 16; i++)
#pragma unroll
        for (int j = 0; j < 4; j++) c[i][j] = 0.f;

    auto issueB = [&](int kc) {
        int s = kc & 1;
        int r = tid >> 4, cu = tid & 15;
        long src = (long)(kc * 16 + r) * 64 + cu * 4;
        CP_ASYNC(smem_u32(&sB[s][0][r][cu * 8]), Wh + src);
        CP_ASYNC(smem_u32(&sB[s][1][r][cu * 8]), Wl + src);
        CP_COMMIT();
    };

    issueB(0);

    for (int kc = 0; kc < 8; kc++) {
        if (kc < 7) {
            issueB(kc + 1);
            asm volatile("cp.async.wait_group 1;" ::: "memory");
        } else {
            asm volatile("cp.async.wait_group 0;" ::: "memory");
        }
        __syncthreads();

        const int s = kc & 1;
        uint32_t ah0, ah1, ah2, ah3, al0, al1, al2, al3;
        ldsm_x4(smem_u32(&sAh[a_r][kc * 8 + a_c4]), ah0, ah1, ah2, ah3);
        ldsm_x4(smem_u32(&sAl[a_r][kc * 8 + a_c4]), al0, al1, al2, al3);

#pragma unroll
        for (int np = 0; np < 8; np++) {
            uint32_t bh0, bh1, bh2, bh3, bl0, bl1, bl2, bl3;
            ldsm_x4_t(smem_u32(&sB[s][0][b_rf][np * 16 + b_c8]),
                      bh0, bh1, bh2, bh3);
            ldsm_x4_t(smem_u32(&sB[s][1][b_rf][np * 16 + b_c8]),
                      bl0, bl1, bl2, bl3);
            mma_bf16(c[2 * np],     ah0, ah1, ah2, ah3, bl0, bl1);
            mma_bf16(c[2 * np],     al0, al1, al2, al3, bh0, bh1);
            mma_bf16(c[2 * np],     ah0, ah1, ah2, ah3, bh0, bh1);
            mma_bf16(c[2 * np + 1], ah0, ah1, ah2, ah3, bl2, bl3);
            mma_bf16(c[2 * np + 1], al0, al1, al2, al3, bh2, bh3);
            mma_bf16(c[2 * np + 1], ah0, ah1, ah2, ah3, bh2, bh3);
        }
        if (kc < 7) __syncthreads();
    }

    const int r_lo = row0 + wm + grp;
    const int r_hi = r_lo + 8;
#pragma unroll
    for (int nt = 0; nt < 16; nt++) {
        int col = nt * 8 + 2 * tig;
        float2 v0 = make_float2(c[nt][0], c[nt][1]);
        float2 v1 = make_float2(c[nt][2], c[nt][3]);
        float2 bb = *reinterpret_cast<const float2*>(&be2[col]);
        v0.x += bb.x; v0.y += bb.y;
        v1.x += bb.x; v1.y += bb.y;
        int ci = nt * 4 + tig;
        uint32_t h0, l0, h1, l1;
        split2(v0.x, v0.y, h0, l0);
        split2(v1.x, v1.y, h1, l1);
        if (r_lo < NN) { Ch[r_lo * 64 + ci] = h0; Cl[r_lo * 64 + ci] = l0; }
        if (r_hi < NN) { Ch[r_hi * 64 + ci] = h1; Cl[r_hi * 64 + ci] = l1; }
    }
}

// ---------------- bf16-split tensor GEMM (R11-proven) ------------------------
__global__ void __launch_bounds__(256, 2)
k_gemm_bf(const uint32_t* __restrict__ Ah, const uint32_t* __restrict__ Al,
          const uint32_t* __restrict__ Wh, const uint32_t* __restrict__ Wl,
          uint32_t* __restrict__ Cfh, int N) {
    __shared__ __align__(16) uint32_t       sA[2][2][128][APITCH];
    __shared__ __align__(16) unsigned short sB[2][2][16][BPITCH];

    const int tid  = threadIdx.x;
    const int wid  = tid >> 5;
    const int lane = tid & 31;
    const int grp  = lane >> 2;
    const int tig  = lane & 3;
    const int row0 = blockIdx.x * 128;
    const int wm   = wid * 16;

    const int b_rf = ((lane >> 3) & 1) * 8 + (lane & 7);
    const int b_c8 = (lane >> 4) * 8;
    const int a_r  = wm + (lane & 15);
    const int a_c4 = (lane >> 4) * 4;

    float c[16][4];
#pragma unroll
    for (int i = 0; i < 16; i++)
#pragma unroll
        for (int j = 0; j < 4; j++) c[i][j] = 0.f;

    auto issue = [&](int kc) {
        int s = kc & 1;
        {
            int r = tid >> 1, q = tid & 1;
            long src = (long)min(row0 + r, N - 1) * 64 + kc * 8 + q * 4;
            CP_ASYNC(smem_u32(&sA[s][0][r][q * 4]), Ah + src);
            CP_ASYNC(smem_u32(&sA[s][1][r][q * 4]), Al + src);
        }
        {
            int r = tid >> 4, cu = tid & 15;
            long src = (long)(kc * 16 + r) * 64 + cu * 4;
            CP_ASYNC(smem_u32(&sB[s][0][r][cu * 8]), Wh + src);
            CP_ASYNC(smem_u32(&sB[s][1][r][cu * 8]), Wl + src);
        }
        CP_COMMIT();
    };

    issue(0);

    for (int kc = 0; kc < 8; kc++) {
        if (kc < 7) {
            issue(kc + 1);
            asm volatile("cp.async.wait_group 1;" ::: "memory");
        } else {
            asm volatile("cp.async.wait_group 0;" ::: "memory");
        }
        __syncthreads();

        const int s = kc & 1;
        uint32_t ah0, ah1, ah2, ah3, al0, al1, al2, al3;
        ldsm_x4(smem_u32(&sA[s][0][a_r][a_c4]), ah0, ah1, ah2, ah3);
        ldsm_x4(smem_u32(&sA[s][1][a_r][a_c4]), al0, al1, al2, al3);

#pragma unroll
        for (int np = 0; np < 8; np++) {
            uint32_t bh0, bh1, bh2, bh3, bl0, bl1, bl2, bl3;
            ldsm_x4_t(smem_u32(&sB[s][0][b_rf][np * 16 + b_c8]),
                      bh0, bh1, bh2, bh3);
            ldsm_x4_t(smem_u32(&sB[s][1][b_rf][np * 16 + b_c8]),
                      bl0, bl1, bl2, bl3);
            mma_bf16(c[2 * np],     ah0, ah1, ah2, ah3, bl0, bl1);
            mma_bf16(c[2 * np],     al0, al1, al2, al3, bh0, bh1);
            mma_bf16(c[2 * np],     ah0, ah1, ah2, ah3, bh0, bh1);
            mma_bf16(c[2 * np + 1], ah0, ah1, ah2, ah3, bl2, bl3);
            mma_bf16(c[2 * np + 1], al0, al1, al2, al3, bh2, bh3);
            mma_bf16(c[2 * np + 1], ah0, ah1, ah2, ah3, bh2, bh3);
        }
        if (kc < 7) __syncthreads();
    }

    const int r_lo = row0 + wm + grp;
    const int r_hi = r_lo + 8;
#pragma unroll
    for (int nt = 0; nt < 16; nt++) {
        int ci = nt * 4 + tig;
        __half2 p0 = __floats2half2_rn(c[nt][0], c[nt][1]);
        __half2 p1 = __floats2half2_rn(c[nt][2], c[nt][3]);
        if (r_lo < N) Cfh[r_lo * 64 + ci] = *reinterpret_cast<uint32_t*>(&p0);
        if (r_hi < N) Cfh[r_hi * 64 + ci] = *reinterpret_cast<uint32_t*>(&p1);
    }
}

// ---------------- fused CSR SpMM over fp16 messages (R11-proven) ------------
__global__ void __launch_bounds__(256)
k_spmm(const float* __restrict__ bias, const int* __restrict__ bidx,
       int do_pool) {
    int gt = blockIdx.x * blockDim.x + threadIdx.x;
    int n  = gt >> 5;
    int l  = gt & 31;
    if (n >= NN) return;

    const uint2* hw2 = reinterpret_cast<const uint2*>(g_hwf);
    float dn = g_dinv[n];
    int start = g_rowptr[n];
    int end   = g_rowptr[n + 1];

    float4 acc;
    {
        uint2 u = hw2[(long)n * 32 + l];
        float2 f0 = __half22float2(*reinterpret_cast<__half2*>(&u.x));
        float2 f1 = __half22float2(*reinterpret_cast<__half2*>(&u.y));
        float d2 = dn * dn;
        acc = make_float4(f0.x * d2, f0.y * d2, f1.x * d2, f1.y * d2);
    }

    for (int base = start; base < end; base += 32) {
        int idx = base + l;
        int s   = 0;
        float dv = 0.f;
        if (idx < end) {
            s  = g_csr[idx];
            dv = g_dinv[s] * dn;
        }
        int m = min(32, end - base);
        for (int j = 0; j < m; j += 4) {
            int   s0 = __shfl_sync(0xffffffff, s,  j);
            int   s1 = __shfl_sync(0xffffffff, s,  j + 1);
            int   s2 = __shfl_sync(0xffffffff, s,  j + 2);
            int   s3 = __shfl_sync(0xffffffff, s,  j + 3);
            float n0 = __shfl_sync(0xffffffff, dv, j);
            float n1 = __shfl_sync(0xffffffff, dv, j + 1);
            float n2 = __shfl_sync(0xffffffff, dv, j + 2);
            float n3 = __shfl_sync(0xffffffff, dv, j + 3);
            uint2 u0 = hw2[(long)s0 * 32 + l];
            uint2 u1 = hw2[(long)s1 * 32 + l];
            uint2 u2 = hw2[(long)s2 * 32 + l];
            uint2 u3 = hw2[(long)s3 * 32 + l];
            float2 a0 = __half22float2(*reinterpret_cast<__half2*>(&u0.x));
            float2 b0 = __half22float2(*reinterpret_cast<__half2*>(&u0.y));
            float2 a1 = __half22float2(*reinterpret_cast<__half2*>(&u1.x));
            float2 b1 = __half22float2(*reinterpret_cast<__half2*>(&u1.y));
            float2 a2 = __half22float2(*reinterpret_cast<__half2*>(&u2.x));
            float2 b2 = __half22float2(*reinterpret_cast<__half2*>(&u2.y));
            float2 a3 = __half22float2(*reinterpret_cast<__half2*>(&u3.x));
            float2 b3 = __half22float2(*reinterpret_cast<__half2*>(&u3.y));
            acc.x += a0.x * n0; acc.y += a0.y * n0;
            acc.z += b0.x * n0; acc.w += b0.y * n0;
            acc.x += a1.x * n1; acc.y += a1.y * n1;
            acc.z += b1.x * n1; acc.w += b1.y * n1;
            acc.x += a2.x * n2; acc.y += a2.y * n2;
            acc.z += b2.x * n2; acc.w += b2.y * n2;
            acc.x += a3.x * n3; acc.y += a3.y * n3;
            acc.z += b3.x * n3; acc.w += b3.y * n3;
        }
    }

    float4 bb = reinterpret_cast<const float4*>(bias)[l];
    acc.x = fmaxf(acc.x + bb.x, 0.f);
    acc.y = fmaxf(acc.y + bb.y, 0.f);
    acc.z = fmaxf(acc.z + bb.z, 0.f);
    acc.w = fmaxf(acc.w + bb.w, 0.f);

    uint32_t h01, l01, h23, l23;
    split2(acc.x, acc.y, h01, l01);
    split2(acc.z, acc.w, h23, l23);
    reinterpret_cast<uint2*>(g_A1h)[(long)n * 32 + l] = make_uint2(h01, h23);
    reinterpret_cast<uint2*>(g_A1l)[(long)n * 32 + l] = make_uint2(l01, l23);

    if (do_pool) {
        int g = bidx[n];
        red_add_f4(&g_pool[g * HID + l * 4], acc);
        if (l == 0) atomicAdd(&g_cnt[g], 1.f);
    }
}

// ---------------- output head ------------------------------------------------
__global__ void k_out(const float* __restrict__ Wo,
                      const float* __restrict__ bo,
                      float* __restrict__ out) {
    int t = blockIdx.x * blockDim.x + threadIdx.x;
    if (t >= NG * OD) return;
    int g = t / OD;
    int o = t % OD;
    float inv = 1.f / fmaxf(g_cnt[g], 1.f);
    float acc = 0.f;
#pragma unroll 8
    for (int k = 0; k < HID; k++)
        acc += g_pool[g * HID + k] * Wo[k * OD + o];
    out[t] = acc * inv + bo[o];
}

// ---------------- launch: fork-join, fused embed+G0 --------------------------
extern "C" void kernel_launch(void* const* d_in, const int* in_sizes, int n_in,
                              void* d_out, int out_size) {
    const float* x    = (const float*)d_in[0];
    const int*   ei   = (const int*)d_in[1];
    const int*   bidx = (const int*)d_in[3];
    const float* We1  = (const float*)d_in[4];
    const float* be1  = (const float*)d_in[5];
    const float* We2  = (const float*)d_in[6];
    const float* be2  = (const float*)d_in[7];
    const float* Wg   = (const float*)d_in[8];
    const float* bg   = (const float*)d_in[9];
    const float* Wo   = (const float*)d_in[10];
    const float* bo   = (const float*)d_in[11];
    float*       out  = (float*)d_out;

    uint32_t *phwf, *pA1h, *pA1l, *pWh, *pWl;
    cudaGetSymbolAddress((void**)&phwf, g_hwf);
    cudaGetSymbolAddress((void**)&pA1h, g_A1h);
    cudaGetSymbolAddress((void**)&pA1l, g_A1l);
    cudaGetSymbolAddress((void**)&pWh,  g_Wh);
    cudaGetSymbolAddress((void**)&pWl,  g_Wl);

    const int TB = 256;
    const int GB = (NN + 127) / 128;
    cudaStream_t s2 = g_hx.s2;

    // fork
    cudaEventRecord(g_hx.eFork, 0);
    cudaStreamWaitEvent(s2, g_hx.eFork, 0);

    // s2: weight pre-split, then CSR build chain
    k_wsplit<<<160, TB, 0, s2>>>(We2, Wg);
    cudaEventRecord(g_hx.eW, s2);
    k_zero <<<(NG * HID + TB - 1) / TB, TB, 0, s2>>>();
    k_deg  <<<(NE + TB - 1) / TB, TB, 0, s2>>>(ei);
    k_scan1<<<NBLK, 1024, 0, s2>>>();
    k_scan2<<<1, 32, 0, s2>>>();
    k_scan3<<<(NN + TB - 1) / TB, TB, 0, s2>>>();
    k_fill <<<(NE + TB - 1) / TB, TB, 0, s2>>>(ei);
    cudaEventRecord(g_hx.eCsr, s2);

    // s0: fused embed1+embed2 -> split A1
    cudaStreamWaitEvent(0, g_hx.eW, 0);
    k_embed_gemm<<<GB, TB>>>(x, We1, be1, pWh, pWl, be2, pA1h, pA1l);

    // GCN layers: gemm (A1 -> hwf) then spmm (hwf -> A1, +pool on last)
    cudaStreamWaitEvent(0, g_hx.eCsr, 0);
    for (int i = 0; i < NL; i++) {
        k_gemm_bf<<<GB, TB>>>(pA1h, pA1l,
                              pWh + (1 + i) * 8192, pWl + (1 + i) * 8192,
                              phwf, NN);
        k_spmm<<<(NN * 32 + TB - 1) / TB, TB>>>(bg + i * HID, bidx,
                                                i == NL - 1 ? 1 : 0);
    }
    k_out<<<(NG * OD + TB - 1) / TB, TB>>>(Wo, bo, out);
}

// round 16
// speedup vs baseline: 1.3862x; 1.0155x over previous
#include <cuda_runtime.h>
#include <cuda_bf16.h>
#include <cuda_fp16.h>
#include <cstdint>

#define NN   50000
#define NE   800000
#define FEAT 16
#define HID  128
#define NL   4
#define NG   1024
#define OD   12
#define NBLK ((NN + 1023) / 1024)
#define BPITCH 136     // ushorts: 272B rows, LDSM.trans conflict-free (proven)
#define APITCH 12      // uint32:  48B rows (gemm A stage, proven)
#define FPITCH 68      // uint32:  272B rows for fused A tile (proven)

// ---------------- streams / events: created at program load -----------------
struct HxStreams {
    cudaStream_t s1, s2;
    cudaEvent_t  eFork, eW, eCsr;
    HxStreams() {
        cudaStreamCreateWithFlags(&s1, cudaStreamNonBlocking);
        cudaStreamCreateWithFlags(&s2, cudaStreamNonBlocking);
        cudaEventCreateWithFlags(&eFork, cudaEventDisableTiming);
        cudaEventCreateWithFlags(&eW,    cudaEventDisableTiming);
        cudaEventCreateWithFlags(&eCsr,  cudaEventDisableTiming);
    }
};
static HxStreams g_hx;

// ---------------- scratch (device globals) ----------------------------------
__device__ uint32_t g_hwf[NN * 64];        // half2-packed GEMM out (spmm input)
__device__ uint32_t g_A1h[NN * 64];        // split bf16 activations
__device__ uint32_t g_A1l[NN * 64];
__device__ uint32_t g_Wh[5 * 8192];
__device__ uint32_t g_Wl[5 * 8192];
__device__ float    g_dinv[NN];
__device__ float    g_pool[NG * HID];
__device__ float    g_cnt[NG];
__device__ int      g_degi[NN];
__device__ int      g_rowptr[NN + 1];
__device__ int      g_fillcnt[NN];
__device__ int      g_csr[NE];
__device__ int      g_bsum[64];

__device__ __forceinline__ void red_add_f4(float* p, float4 v) {
    asm volatile("red.global.add.v4.f32 [%0], {%1,%2,%3,%4};"
                 :: "l"(p), "f"(v.x), "f"(v.y), "f"(v.z), "f"(v.w)
                 : "memory");
}

__device__ __forceinline__ uint32_t smem_u32(const void* p) {
    uint32_t a;
    asm("{ .reg .u64 t; cvta.to.shared.u64 t, %1; cvt.u32.u64 %0, t; }"
        : "=r"(a) : "l"(p));
    return a;
}

__device__ __forceinline__ uint32_t pack_bf16(float x, float y) {
    uint32_t r;
    asm("cvt.rn.bf16x2.f32 %0, %1, %2;" : "=r"(r) : "f"(y), "f"(x));
    return r;
}
__device__ __forceinline__ void split2(float x, float y, uint32_t& h, uint32_t& l) {
    h = pack_bf16(x, y);
    float hx = __uint_as_float(h << 16);
    float hy = __uint_as_float(h & 0xffff0000u);
    l = pack_bf16(x - hx, y - hy);
}

__device__ __forceinline__ void ldsm_x4(uint32_t addr, uint32_t& r0,
                                        uint32_t& r1, uint32_t& r2, uint32_t& r3) {
    asm volatile("ldmatrix.sync.aligned.m8n8.x4.shared.b16 {%0,%1,%2,%3}, [%4];"
                 : "=r"(r0), "=r"(r1), "=r"(r2), "=r"(r3) : "r"(addr));
}
__device__ __forceinline__ void ldsm_x4_t(uint32_t addr, uint32_t& r0,
                                          uint32_t& r1, uint32_t& r2, uint32_t& r3) {
    asm volatile("ldmatrix.sync.aligned.m8n8.x4.trans.shared.b16 {%0,%1,%2,%3}, [%4];"
                 : "=r"(r0), "=r"(r1), "=r"(r2), "=r"(r3) : "r"(addr));
}

__device__ __forceinline__ void mma_bf16(float c[4],
                                         uint32_t a0, uint32_t a1,
                                         uint32_t a2, uint32_t a3,
                                         uint32_t b0, uint32_t b1) {
    asm volatile(
        "mma.sync.aligned.m16n8k16.row.col.f32.bf16.bf16.f32 "
        "{%0,%1,%2,%3}, {%4,%5,%6,%7}, {%8,%9}, {%0,%1,%2,%3};"
        : "+f"(c[0]), "+f"(c[1]), "+f"(c[2]), "+f"(c[3])
        : "r"(a0), "r"(a1), "r"(a2), "r"(a3), "r"(b0), "r"(b1));
}

#define CP_ASYNC(dst, src) \
    asm volatile("cp.async.cg.shared.global [%0], [%1], 16;" \
                 :: "r"(dst), "l"(src) : "memory")
#define CP_COMMIT() asm volatile("cp.async.commit_group;" ::: "memory")

// ---------------- init / CSR build -----------------------------------------
__global__ void k_zero() {
    int i = blockIdx.x * blockDim.x + threadIdx.x;
    if (i < NG * HID) g_pool[i] = 0.f;
    if (i < NG)       g_cnt[i]  = 0.f;
    if (i < NN) { g_degi[i] = 0; g_fillcnt[i] = 0; }
}

__global__ void k_deg(const int* __restrict__ ei) {
    int e = blockIdx.x * blockDim.x + threadIdx.x;
    if (e < NE) atomicAdd(&g_degi[ei[NE + e]], 1);
}

__global__ void __launch_bounds__(1024)
k_scan1() {
    __shared__ int ws[32];
    int t    = threadIdx.x;
    int lane = t & 31;
    int w    = t >> 5;
    int i    = blockIdx.x * 1024 + t;
    int d = (i < NN) ? g_degi[i] : 0;
    int v = d;
#pragma unroll
    for (int o = 1; o < 32; o <<= 1) {
        int u = __shfl_up_sync(0xffffffff, v, o);
        if (lane >= o) v += u;
    }
    if (lane == 31) ws[w] = v;
    __syncthreads();
    if (w == 0) {
        int x = ws[lane];
#pragma unroll
        for (int o = 1; o < 32; o <<= 1) {
            int u = __shfl_up_sync(0xffffffff, x, o);
            if (lane >= o) x += u;
        }
        ws[lane] = x;
    }
    __syncthreads();
    int incl = v + (w ? ws[w - 1] : 0);
    if (i < NN) g_rowptr[i] = incl;
    if (t == 1023) g_bsum[blockIdx.x] = incl;
}

__global__ void k_scan2() {
    int lane = threadIdx.x;
    int v0 = (lane < NBLK) ? g_bsum[lane] : 0;
    int v1 = (32 + lane < NBLK) ? g_bsum[32 + lane] : 0;
    int s0 = v0, s1 = v1;
#pragma unroll
    for (int o = 1; o < 32; o <<= 1) {
        int u0 = __shfl_up_sync(0xffffffff, s0, o);
        int u1 = __shfl_up_sync(0xffffffff, s1, o);
        if (lane >= o) { s0 += u0; s1 += u1; }
    }
    int tot0 = __shfl_sync(0xffffffff, s0, 31);
    if (lane < NBLK)      g_bsum[lane]      = s0 - v0;
    if (32 + lane < NBLK) g_bsum[32 + lane] = s1 - v1 + tot0;
}

__global__ void k_scan3() {
    int i = blockIdx.x * blockDim.x + threadIdx.x;
    if (i < NN) {
        int incl = g_rowptr[i];
        int d    = g_degi[i];
        g_rowptr[i] = incl - d + g_bsum[i >> 10];
        g_dinv[i]   = rsqrtf((float)d + 1.f);
    }
    if (i == 0) g_rowptr[NN] = NE;
}

__global__ void k_fill(const int* __restrict__ ei) {
    int e = blockIdx.x * blockDim.x + threadIdx.x;
    if (e >= NE) return;
    int s = ei[e];
    int d = ei[NE + e];
    int pos = g_rowptr[d] + atomicAdd(&g_fillcnt[d], 1);
    g_csr[pos] = s;
}

// ---------------- weight pre-split ------------------------------------------
__global__ void k_wsplit(const float* __restrict__ We2,
                         const float* __restrict__ Wg) {
    int i = blockIdx.x * blockDim.x + threadIdx.x;
    if (i >= 5 * 8192) return;
    int mat = i >> 13;
    int off = i & 8191;
    const float* src = (mat == 0) ? (We2 + off * 2)
                                  : (Wg + (mat - 1) * 16384 + off * 2);
    uint32_t h, l;
    split2(src[0], src[1], h, l);
    g_Wh[i] = h;
    g_Wl[i] = l;
}

// ---------------- FUSED embed: A1 = (relu(x@We1+be1)) @ We2 + be2 (split) ---
__global__ void __launch_bounds__(256, 2)
k_embed_gemm(const float* __restrict__ x,
             const float* __restrict__ We1, const float* __restrict__ be1,
             const uint32_t* __restrict__ Wh, const uint32_t* __restrict__ Wl,
             const float* __restrict__ be2,
             uint32_t* __restrict__ Ch, uint32_t* __restrict__ Cl) {
    __shared__ __align__(16) uint32_t sAh[128][FPITCH];
    __shared__ __align__(16) uint32_t sAl[128][FPITCH];
    __shared__ __align__(16) char     sMix[17408];        // Ws+xs | sB

    float (*Ws)[HID]     = reinterpret_cast<float(*)[HID]>(sMix);
    float (*xs)[FEAT+1]  = reinterpret_cast<float(*)[FEAT+1]>(sMix + 8192);
    typedef unsigned short (*SBt)[2][16][BPITCH];
    SBt sB = reinterpret_cast<SBt>(sMix);

    const int tid  = threadIdx.x;
    const int wid  = tid >> 5;
    const int lane = tid & 31;
    const int grp  = lane >> 2;
    const int tig  = lane & 3;
    const int row0 = blockIdx.x * 128;
    const int wm   = wid * 16;

    // ---- phase 1: embed 128 nodes ----
    {
        const float4* Wv = reinterpret_cast<const float4*>(We1);
        float4* Wsv = reinterpret_cast<float4*>(&Ws[0][0]);
        Wsv[tid]       = Wv[tid];
        Wsv[tid + 256] = Wv[tid + 256];
    }
#pragma unroll
    for (int p = 0; p < 2; p++) {
        int u    = tid + p * 256;
        int node = row0 + (u >> 2);
        float4 v = make_float4(0.f, 0.f, 0.f, 0.f);
        if (node < NN)
            v = reinterpret_cast<const float4*>(x)[node * 4 + (u & 3)];
        int li = u >> 2, q = u & 3;
        xs[li][q * 4 + 0] = v.x;
        xs[li][q * 4 + 1] = v.y;
        xs[li][q * 4 + 2] = v.z;
        xs[li][q * 4 + 3] = v.w;
    }
    __syncthreads();

    {
        const int rg = tid >> 4;
        const int cg = tid & 15;
        float acc[8][8];
        float bb[8];
#pragma unroll
        for (int j = 0; j < 8; j++) bb[j] = be1[cg * 8 + j];
#pragma unroll
        for (int v = 0; v < 8; v++)
#pragma unroll
            for (int j = 0; j < 8; j++) acc[v][j] = bb[j];

#pragma unroll
        for (int k = 0; k < FEAT; k++) {
            float4 w0 = *reinterpret_cast<const float4*>(&Ws[k][cg * 8]);
            float4 w1 = *reinterpret_cast<const float4*>(&Ws[k][cg * 8 + 4]);
#pragma unroll
            for (int v = 0; v < 8; v++) {
                float xv = xs[rg * 8 + v][k];
                acc[v][0] += xv * w0.x; acc[v][1] += xv * w0.y;
                acc[v][2] += xv * w0.z; acc[v][3] += xv * w0.w;
                acc[v][4] += xv * w1.x; acc[v][5] += xv * w1.y;
                acc[v][6] += xv * w1.z; acc[v][7] += xv * w1.w;
            }
        }
        __syncthreads();
#pragma unroll
        for (int v = 0; v < 8; v++) {
            int r = rg * 8 + v;
#pragma unroll
            for (int q = 0; q < 4; q++) {
                uint32_t h, l;
                split2(fmaxf(acc[v][2 * q], 0.f), fmaxf(acc[v][2 * q + 1], 0.f),
                       h, l);
                sAh[r][cg * 4 + q] = h;
                sAl[r][cg * 4 + q] = l;
            }
        }
    }
    __syncthreads();

    // ---- phase 2: gemm with We2 from smem A, cp.async B ----
    const int b_rf = ((lane >> 3) & 1) * 8 + (lane & 7);
    const int b_c8 = (lane >> 4) * 8;
    const int a_r  = wm + (lane & 15);
    const int a_c4 = (lane >> 4) * 4;

    float c[16][4];
#pragma unroll
    for (int i = 0; i < 16; i++)
#pragma unroll
        for (int j = 0; j < 4; j++) c[i][j] = 0.f;

    auto issueB = [&](int kc) {
        int s = kc & 1;
        int r = tid >> 4, cu = tid & 15;
        long src = (long)(kc * 16 + r) * 64 + cu * 4;
        CP_ASYNC(smem_u32(&sB[s][0][r][cu * 8]), Wh + src);
        CP_ASYNC(smem_u32(&sB[s][1][r][cu * 8]), Wl + src);
        CP_COMMIT();
    };

    issueB(0);

    for (int kc = 0; kc < 8; kc++) {
        if (kc < 7) {
            issueB(kc + 1);
            asm volatile("cp.async.wait_group 1;" ::: "memory");
        } else {
            asm volatile("cp.async.wait_group 0;" ::: "memory");
        }
        __syncthreads();

        const int s = kc & 1;
        uint32_t ah0, ah1, ah2, ah3, al0, al1, al2, al3;
        ldsm_x4(smem_u32(&sAh[a_r][kc * 8 + a_c4]), ah0, ah1, ah2, ah3);
        ldsm_x4(smem_u32(&sAl[a_r][kc * 8 + a_c4]), al0, al1, al2, al3);

#pragma unroll
        for (int np = 0; np < 8; np++) {
            uint32_t bh0, bh1, bh2, bh3, bl0, bl1, bl2, bl3;
            ldsm_x4_t(smem_u32(&sB[s][0][b_rf][np * 16 + b_c8]),
                      bh0, bh1, bh2, bh3);
            ldsm_x4_t(smem_u32(&sB[s][1][b_rf][np * 16 + b_c8]),
                      bl0, bl1, bl2, bl3);
            mma_bf16(c[2 * np],     ah0, ah1, ah2, ah3, bl0, bl1);
            mma_bf16(c[2 * np],     al0, al1, al2, al3, bh0, bh1);
            mma_bf16(c[2 * np],     ah0, ah1, ah2, ah3, bh0, bh1);
            mma_bf16(c[2 * np + 1], ah0, ah1, ah2, ah3, bl2, bl3);
            mma_bf16(c[2 * np + 1], al0, al1, al2, al3, bh2, bh3);
            mma_bf16(c[2 * np + 1], ah0, ah1, ah2, ah3, bh2, bh3);
        }
        if (kc < 7) __syncthreads();
    }

    const int r_lo = row0 + wm + grp;
    const int r_hi = r_lo + 8;
#pragma unroll
    for (int nt = 0; nt < 16; nt++) {
        int col = nt * 8 + 2 * tig;
        float2 v0 = make_float2(c[nt][0], c[nt][1]);
        float2 v1 = make_float2(c[nt][2], c[nt][3]);
        float2 bb = *reinterpret_cast<const float2*>(&be2[col]);
        v0.x += bb.x; v0.y += bb.y;
        v1.x += bb.x; v1.y += bb.y;
        int ci = nt * 4 + tig;
        uint32_t h0, l0, h1, l1;
        split2(v0.x, v0.y, h0, l0);
        split2(v1.x, v1.y, h1, l1);
        if (r_lo < NN) { Ch[r_lo * 64 + ci] = h0; Cl[r_lo * 64 + ci] = l0; }
        if (r_hi < NN) { Ch[r_hi * 64 + ci] = h1; Cl[r_hi * 64 + ci] = l1; }
    }
}

// ---------------- bf16-split tensor GEMM, BK=32 (chunk pairs per stage) ------
__global__ void __launch_bounds__(256, 2)
k_gemm_bf(const uint32_t* __restrict__ Ah, const uint32_t* __restrict__ Al,
          const uint32_t* __restrict__ Wh, const uint32_t* __restrict__ Wl,
          uint32_t* __restrict__ Cfh, int N) {
    __shared__ __align__(16) uint32_t       sAh[2][2][128][APITCH];
    __shared__ __align__(16) uint32_t       sAl[2][2][128][APITCH];
    __shared__ __align__(16) unsigned short sBh[2][2][16][BPITCH];
    __shared__ __align__(16) unsigned short sBl[2][2][16][BPITCH];

    const int tid  = threadIdx.x;
    const int wid  = tid >> 5;
    const int lane = tid & 31;
    const int grp  = lane >> 2;
    const int tig  = lane & 3;
    const int row0 = blockIdx.x * 128;
    const int wm   = wid * 16;

    const int b_rf = ((lane >> 3) & 1) * 8 + (lane & 7);
    const int b_c8 = (lane >> 4) * 8;
    const int a_r  = wm + (lane & 15);
    const int a_c4 = (lane >> 4) * 4;

    float c[16][4];
#pragma unroll
    for (int i = 0; i < 16; i++)
#pragma unroll
        for (int j = 0; j < 4; j++) c[i][j] = 0.f;

    // stage = pair of 16-k chunks
    auto issue = [&](int p) {
        int s = p & 1;
#pragma unroll
        for (int sub = 0; sub < 2; sub++) {
            int kc = p * 2 + sub;
            {
                int r = tid >> 1, q = tid & 1;
                long src = (long)min(row0 + r, N - 1) * 64 + kc * 8 + q * 4;
                CP_ASYNC(smem_u32(&sAh[s][sub][r][q * 4]), Ah + src);
                CP_ASYNC(smem_u32(&sAl[s][sub][r][q * 4]), Al + src);
            }
            {
                int r = tid >> 4, cu = tid & 15;
                long src = (long)(kc * 16 + r) * 64 + cu * 4;
                CP_ASYNC(smem_u32(&sBh[s][sub][r][cu * 8]), Wh + src);
                CP_ASYNC(smem_u32(&sBl[s][sub][r][cu * 8]), Wl + src);
            }
        }
        CP_COMMIT();
    };

    issue(0);

    for (int p = 0; p < 4; p++) {
        if (p < 3) {
            issue(p + 1);
            asm volatile("cp.async.wait_group 1;" ::: "memory");
        } else {
            asm volatile("cp.async.wait_group 0;" ::: "memory");
        }
        __syncthreads();

        const int s = p & 1;
#pragma unroll
        for (int sub = 0; sub < 2; sub++) {
            uint32_t ah0, ah1, ah2, ah3, al0, al1, al2, al3;
            ldsm_x4(smem_u32(&sAh[s][sub][a_r][a_c4]), ah0, ah1, ah2, ah3);
            ldsm_x4(smem_u32(&sAl[s][sub][a_r][a_c4]), al0, al1, al2, al3);

#pragma unroll
            for (int np = 0; np < 8; np++) {
                uint32_t bh0, bh1, bh2, bh3, bl0, bl1, bl2, bl3;
                ldsm_x4_t(smem_u32(&sBh[s][sub][b_rf][np * 16 + b_c8]),
                          bh0, bh1, bh2, bh3);
                ldsm_x4_t(smem_u32(&sBl[s][sub][b_rf][np * 16 + b_c8]),
                          bl0, bl1, bl2, bl3);
                mma_bf16(c[2 * np],     ah0, ah1, ah2, ah3, bl0, bl1);
                mma_bf16(c[2 * np],     al0, al1, al2, al3, bh0, bh1);
                mma_bf16(c[2 * np],     ah0, ah1, ah2, ah3, bh0, bh1);
                mma_bf16(c[2 * np + 1], ah0, ah1, ah2, ah3, bl2, bl3);
                mma_bf16(c[2 * np + 1], al0, al1, al2, al3, bh2, bh3);
                mma_bf16(c[2 * np + 1], ah0, ah1, ah2, ah3, bh2, bh3);
            }
        }
        if (p < 3) __syncthreads();
    }

    const int r_lo = row0 + wm + grp;
    const int r_hi = r_lo + 8;
#pragma unroll
    for (int nt = 0; nt < 16; nt++) {
        int ci = nt * 4 + tig;
        __half2 p0 = __floats2half2_rn(c[nt][0], c[nt][1]);
        __half2 p1 = __floats2half2_rn(c[nt][2], c[nt][3]);
        if (r_lo < N) Cfh[r_lo * 64 + ci] = *reinterpret_cast<uint32_t*>(&p0);
        if (r_hi < N) Cfh[r_hi * 64 + ci] = *reinterpret_cast<uint32_t*>(&p1);
    }
}

// ---------------- fused CSR SpMM over fp16 messages (R11-proven) ------------
// do_pool: pool only (last layer, no A1 write); else write split A1.
__global__ void __launch_bounds__(256)
k_spmm(const float* __restrict__ bias, const int* __restrict__ bidx,
       int do_pool) {
    int gt = blockIdx.x * blockDim.x + threadIdx.x;
    int n  = gt >> 5;
    int l  = gt & 31;
    if (n >= NN) return;

    const uint2* hw2 = reinterpret_cast<const uint2*>(g_hwf);
    float dn = g_dinv[n];
    int start = g_rowptr[n];
    int end   = g_rowptr[n + 1];

    float4 acc;
    {
        uint2 u = hw2[(long)n * 32 + l];
        float2 f0 = __half22float2(*reinterpret_cast<__half2*>(&u.x));
        float2 f1 = __half22float2(*reinterpret_cast<__half2*>(&u.y));
        float d2 = dn * dn;
        acc = make_float4(f0.x * d2, f0.y * d2, f1.x * d2, f1.y * d2);
    }

    for (int base = start; base < end; base += 32) {
        int idx = base + l;
        int s   = 0;
        float dv = 0.f;
        if (idx < end) {
            s  = g_csr[idx];
            dv = g_dinv[s] * dn;
        }
        int m = min(32, end - base);
        for (int j = 0; j < m; j += 4) {
            int   s0 = __shfl_sync(0xffffffff, s,  j);
            int   s1 = __shfl_sync(0xffffffff, s,  j + 1);
            int   s2 = __shfl_sync(0xffffffff, s,  j + 2);
            int   s3 = __shfl_sync(0xffffffff, s,  j + 3);
            float n0 = __shfl_sync(0xffffffff, dv, j);
            float n1 = __shfl_sync(0xffffffff, dv, j + 1);
            float n2 = __shfl_sync(0xffffffff, dv, j + 2);
            float n3 = __shfl_sync(0xffffffff, dv, j + 3);
            uint2 u0 = hw2[(long)s0 * 32 + l];
            uint2 u1 = hw2[(long)s1 * 32 + l];
            uint2 u2 = hw2[(long)s2 * 32 + l];
            uint2 u3 = hw2[(long)s3 * 32 + l];
            float2 a0 = __half22float2(*reinterpret_cast<__half2*>(&u0.x));
            float2 b0 = __half22float2(*reinterpret_cast<__half2*>(&u0.y));
            float2 a1 = __half22float2(*reinterpret_cast<__half2*>(&u1.x));
            float2 b1 = __half22float2(*reinterpret_cast<__half2*>(&u1.y));
            float2 a2 = __half22float2(*reinterpret_cast<__half2*>(&u2.x));
            float2 b2 = __half22float2(*reinterpret_cast<__half2*>(&u2.y));
            float2 a3 = __half22float2(*reinterpret_cast<__half2*>(&u3.x));
            float2 b3 = __half22float2(*reinterpret_cast<__half2*>(&u3.y));
            acc.x += a0.x * n0; acc.y += a0.y * n0;
            acc.z += b0.x * n0; acc.w += b0.y * n0;
            acc.x += a1.x * n1; acc.y += a1.y * n1;
            acc.z += b1.x * n1; acc.w += b1.y * n1;
            acc.x += a2.x * n2; acc.y += a2.y * n2;
            acc.z += b2.x * n2; acc.w += b2.y * n2;
            acc.x += a3.x * n3; acc.y += a3.y * n3;
            acc.z += b3.x * n3; acc.w += b3.y * n3;
        }
    }

    float4 bb = reinterpret_cast<const float4*>(bias)[l];
    acc.x = fmaxf(acc.x + bb.x, 0.f);
    acc.y = fmaxf(acc.y + bb.y, 0.f);
    acc.z = fmaxf(acc.z + bb.z, 0.f);
    acc.w = fmaxf(acc.w + bb.w, 0.f);

    if (do_pool) {
        // last layer: pooling only, A1 not consumed afterwards
        int g = bidx[n];
        red_add_f4(&g_pool[g * HID + l * 4], acc);
        if (l == 0) atomicAdd(&g_cnt[g], 1.f);
    } else {
        uint32_t h01, l01, h23, l23;
        split2(acc.x, acc.y, h01, l01);
        split2(acc.z, acc.w, h23, l23);
        reinterpret_cast<uint2*>(g_A1h)[(long)n * 32 + l] = make_uint2(h01, h23);
        reinterpret_cast<uint2*>(g_A1l)[(long)n * 32 + l] = make_uint2(l01, l23);
    }
}

// ---------------- output head ------------------------------------------------
__global__ void k_out(const float* __restrict__ Wo,
                      const float* __restrict__ bo,
                      float* __restrict__ out) {
    int t = blockIdx.x * blockDim.x + threadIdx.x;
    if (t >= NG * OD) return;
    int g = t / OD;
    int o = t % OD;
    float inv = 1.f / fmaxf(g_cnt[g], 1.f);
    float acc = 0.f;
#pragma unroll 8
    for (int k = 0; k < HID; k++)
        acc += g_pool[g * HID + k] * Wo[k * OD + o];
    out[t] = acc * inv + bo[o];
}

// ---------------- launch: fork-join, fused embed+G0, BK=32 gemms -------------
extern "C" void kernel_launch(void* const* d_in, const int* in_sizes, int n_in,
                              void* d_out, int out_size) {
    const float* x    = (const float*)d_in[0];
    const int*   ei   = (const int*)d_in[1];
    const int*   bidx = (const int*)d_in[3];
    const float* We1  = (const float*)d_in[4];
    const float* be1  = (const float*)d_in[5];
    const float* We2  = (const float*)d_in[6];
    const float* be2  = (const float*)d_in[7];
    const float* Wg   = (const float*)d_in[8];
    const float* bg   = (const float*)d_in[9];
    const float* Wo   = (const float*)d_in[10];
    const float* bo   = (const float*)d_in[11];
    float*       out  = (float*)d_out;

    uint32_t *phwf, *pA1h, *pA1l, *pWh, *pWl;
    cudaGetSymbolAddress((void**)&phwf, g_hwf);
    cudaGetSymbolAddress((void**)&pA1h, g_A1h);
    cudaGetSymbolAddress((void**)&pA1l, g_A1l);
    cudaGetSymbolAddress((void**)&pWh,  g_Wh);
    cudaGetSymbolAddress((void**)&pWl,  g_Wl);

    const int TB = 256;
    const int GB = (NN + 127) / 128;
    cudaStream_t s2 = g_hx.s2;

    // fork
    cudaEventRecord(g_hx.eFork, 0);
    cudaStreamWaitEvent(s2, g_hx.eFork, 0);

    // s2: weight pre-split, then CSR build chain
    k_wsplit<<<160, TB, 0, s2>>>(We2, Wg);
    cudaEventRecord(g_hx.eW, s2);
    k_zero <<<(NG * HID + TB - 1) / TB, TB, 0, s2>>>();
    k_deg  <<<(NE + TB - 1) / TB, TB, 0, s2>>>(ei);
    k_scan1<<<NBLK, 1024, 0, s2>>>();
    k_scan2<<<1, 32, 0, s2>>>();
    k_scan3<<<(NN + TB - 1) / TB, TB, 0, s2>>>();
    k_fill <<<(NE + TB - 1) / TB, TB, 0, s2>>>(ei);
    cudaEventRecord(g_hx.eCsr, s2);

    // s0: fused embed1+embed2 -> split A1
    cudaStreamWaitEvent(0, g_hx.eW, 0);
    k_embed_gemm<<<GB, TB>>>(x, We1, be1, pWh, pWl, be2, pA1h, pA1l);

    // GCN layers: gemm (A1 -> hwf) then spmm (hwf -> A1 / pool on last)
    cudaStreamWaitEvent(0, g_hx.eCsr, 0);
    for (int i = 0; i < NL; i++) {
        k_gemm_bf<<<GB, TB>>>(pA1h, pA1l,
                              pWh + (1 + i) * 8192, pWl + (1 + i) * 8192,
                              phwf, NN);
        k_spmm<<<(NN * 32 + TB - 1) / TB, TB>>>(bg + i * HID, bidx,
                                                i == NL - 1 ? 1 : 0);
    }
    k_out<<<(NG * OD + TB - 1) / TB, TB>>>(Wo, bo, out);
}